// round 1
// baseline (speedup 1.0000x reference)
#include <cuda_runtime.h>
#include <math.h>
#include <stdint.h>
#include <stddef.h>

#define BB 16
#define TT 2048
#define HH 768
#define G4 3072
#define NH 12
#define HD 64

// ---------------- recurrent kernel config ----------------
#define RGRID 128
#define RC 6                 // hidden units per block (768/128)
#define RROWS 24             // 4 gates * RC
#define RTHREADS 128
// smem: ws 24*768, hs 16*772 (padded), ps 24*16
#define RECUR_SMEM_FLOATS (RROWS*HH + BB*772 + RROWS*BB)
#define RECUR_SMEM_BYTES (RECUR_SMEM_FLOATS * 4)

// ---------------- projection kernel config ----------------
#define PGT 128              // g rows per block
#define PKC 32               // k chunk
#define PTHREADS 128
#define PCHUNKS (HH / PKC)   // 24
// smem: xs 16*772 floats + wbuf 2*128*32 floats
#define PROJ_SMEM_FLOATS (BB*772 + 2*PGT*PKC)
#define PROJ_SMEM_BYTES (PROJ_SMEM_FLOATS * 4)

// ---------------- global scratch ----------------
__device__ float g_xg[(size_t)TT * G4 * BB];   // [t][g][b]  ~403 MB
__device__ float g_h[2][BB * HH];              // [buf][b][k]
__device__ unsigned g_bar;

// =======================================================================
// init: zero h(-1) buffer and the barrier counter (must happen per launch)
// =======================================================================
__global__ void init_kernel() {
    int i = blockIdx.x * blockDim.x + threadIdx.x;
    if (i == 0) g_bar = 0u;
    if (i < BB * HH) g_h[0][i] = 0.0f;
}

// =======================================================================
// projection: xg[t][g][b] = sum_d W_ih[g][d]*x[b][t][d] + b_ih[g] + b_hh[g]
// x[b][t][d] = state[b, d>>6, t, d&63]
// grid: (G4/PGT=24, TT), 128 threads
// =======================================================================
__global__ void __launch_bounds__(PTHREADS)
proj_kernel(const float* __restrict__ state,
            const float* __restrict__ W_ih,
            const float* __restrict__ b_ih,
            const float* __restrict__ b_hh) {
    extern __shared__ float smem[];
    float*  xs    = smem;                         // [16][772]
    float4* xs4   = (float4*)xs;                  // pitch 193 f4
    float4* wbuf  = (float4*)(smem + BB * 772);   // 2 * 1024 float4 (chunked, swizzled)

    const int t   = blockIdx.y;
    const int g0  = blockIdx.x * PGT;
    const int tid = threadIdx.x;

    // load x slice for this t into smem (all 16 batches, 768 dims)
    const float4* st4 = (const float4*)state;
    #pragma unroll 4
    for (int fi = tid; fi < BB * 192; fi += PTHREADS) {
        int b  = fi / 192;
        int d4 = fi % 192;           // float4 index within 768 dims
        int head = d4 >> 4;          // 16 f4 per head (64 floats)
        int dl   = d4 & 15;
        float4 v = st4[(((size_t)(b * NH + head)) * TT + t) * 16 + dl];
        xs4[b * 193 + d4] = v;
    }

    // prefetch weight chunk 0 (XOR-swizzled so compute LDS.128 is conflict-free)
    const float4* w4 = (const float4*)W_ih;       // rows of 192 f4
    for (int idx = tid; idx < PGT * 8; idx += PTHREADS) {
        int row = idx >> 3, c4 = idx & 7;
        wbuf[row * 8 + (c4 ^ ((row >> 2) & 7))] = w4[(size_t)(g0 + row) * 192 + c4];
    }

    const int tb = tid & 3;          // 4 b's per thread: b = 4*tb + j
    const int tg = tid >> 2;         // 0..31 : 4 g rows per thread
    float acc[4][4];
    #pragma unroll
    for (int i = 0; i < 4; i++)
        #pragma unroll
        for (int j = 0; j < 4; j++) acc[i][j] = 0.0f;

    int buf = 0;
    for (int c = 0; c < PCHUNKS; ++c) {
        __syncthreads();
        if (c + 1 < PCHUNKS) {
            int nb = buf ^ 1;
            #pragma unroll 2
            for (int idx = tid; idx < PGT * 8; idx += PTHREADS) {
                int row = idx >> 3, c4 = idx & 7;
                wbuf[nb * 1024 + row * 8 + (c4 ^ ((row >> 2) & 7))] =
                    w4[(size_t)(g0 + row) * 192 + (c + 1) * 8 + c4];
            }
        }
        const float4* wb = wbuf + buf * 1024;
        #pragma unroll
        for (int c4 = 0; c4 < 8; ++c4) {
            float4 wv[4];
            #pragma unroll
            for (int i = 0; i < 4; i++)
                wv[i] = wb[(4 * tg + i) * 8 + (c4 ^ (tg & 7))];
            float4 xv[4];
            #pragma unroll
            for (int j = 0; j < 4; j++)
                xv[j] = xs4[(4 * tb + j) * 193 + c * 8 + c4];
            #pragma unroll
            for (int i = 0; i < 4; i++) {
                #pragma unroll
                for (int j = 0; j < 4; j++) {
                    acc[i][j] += wv[i].x * xv[j].x;
                    acc[i][j] += wv[i].y * xv[j].y;
                    acc[i][j] += wv[i].z * xv[j].z;
                    acc[i][j] += wv[i].w * xv[j].w;
                }
            }
        }
        buf ^= 1;
    }

    // write xg[t][g][b] (+ bias), float4 over 4 consecutive b
    float4* xg4 = (float4*)g_xg;
    #pragma unroll
    for (int i = 0; i < 4; i++) {
        int g = g0 + 4 * tg + i;
        float bias = b_ih[g] + b_hh[g];
        float4 o;
        o.x = acc[i][0] + bias;
        o.y = acc[i][1] + bias;
        o.z = acc[i][2] + bias;
        o.w = acc[i][3] + bias;
        xg4[((size_t)t * G4 + g) * 4 + tb] = o;
    }
}

// =======================================================================
// recurrence: 128 persistent CTAs, each owns 6 hidden units (24 W_hh rows
// resident in SMEM). Per step: global spin barrier, load h(t-1) (49KB),
// 24x16 GEMV chunk, gate nonlinearity, write h(t) + output.
// =======================================================================
__global__ void __launch_bounds__(RTHREADS)
recur_kernel(const float* __restrict__ W_hh, float* __restrict__ out) {
    extern __shared__ float smem[];
    float*  ws  = smem;                         // [24][768]
    float4* ws4 = (float4*)ws;                  // pitch 192 f4
    float*  hs  = smem + RROWS * HH;            // [16][772]
    float4* hs4 = (float4*)hs;                  // pitch 193 f4
    float*  ps  = hs + BB * 772;                // [24][16]

    const int blk = blockIdx.x;
    const int tid = threadIdx.x;
    const int b   = tid & 15;
    const int gg  = tid >> 4;                   // 0..7

    // load this block's 24 W_hh rows into smem (row r = gate*6+u)
    const float4* wh4 = (const float4*)W_hh;
    #pragma unroll 4
    for (int idx = tid; idx < RROWS * 192; idx += RTHREADS) {
        int r  = idx / 192, c4 = idx % 192;
        int R  = (r / RC) * HH + blk * RC + (r % RC);   // global W_hh row
        ws4[r * 192 + c4] = wh4[(size_t)R * 192 + c4];
    }

    // rows owned by this thread for the GEMV: gg, gg+8, gg+16
    const int r0 = gg, r1 = gg + 8, r2 = gg + 16;
    const size_t xb0 = ((size_t)((r0 / RC) * HH + blk * RC + (r0 % RC))) * BB + b;
    const size_t xb1 = ((size_t)((r1 / RC) * HH + blk * RC + (r1 % RC))) * BB + b;
    const size_t xb2 = ((size_t)((r2 / RC) * HH + blk * RC + (r2 % RC))) * BB + b;

    // cell state for elementwise threads (tid < 96): b = tid&15, u = tid>>4
    float cstate = 0.0f;
    const int eb = tid & 15;
    const int eu = tid >> 4;   // 0..5 valid when tid < 96

    __syncthreads();

    for (int t = 0; t < TT; ++t) {
        // prefetch xg contributions (independent of the barrier)
        const size_t xoff = (size_t)t * G4 * BB;
        float a0 = g_xg[xoff + xb0];
        float a1 = g_xg[xoff + xb1];
        float a2 = g_xg[xoff + xb2];

        // wait for all blocks to finish step t-1
        if (t > 0 && tid == 0) {
            unsigned target = (unsigned)t * RGRID;
            while (*(volatile unsigned*)&g_bar < target) { }
            __threadfence();
        }
        __syncthreads();

        // load h(t-1) into smem (L2-direct to avoid stale L1)
        const int pb = t & 1;
        const float4* gh4 = (const float4*)g_h[pb];
        #pragma unroll 6
        for (int idx = tid; idx < BB * 192; idx += RTHREADS) {
            int bb = idx / 192, c4 = idx % 192;
            hs4[bb * 193 + c4] = __ldcg(gh4 + bb * 192 + c4);
        }
        __syncthreads();

        // GEMV: 3 dot products of length 768 per thread
        float s0 = a0, s1 = a1, s2 = a2;
        const float4* hrow = hs4 + b * 193;
        const float4* w0 = ws4 + r0 * 192;
        const float4* w1 = ws4 + r1 * 192;
        const float4* w2 = ws4 + r2 * 192;
        #pragma unroll 8
        for (int k4 = 0; k4 < 192; ++k4) {
            float4 hv = hrow[k4];
            float4 v0 = w0[k4];
            float4 v1 = w1[k4];
            float4 v2 = w2[k4];
            s0 += v0.x * hv.x; s0 += v0.y * hv.y; s0 += v0.z * hv.z; s0 += v0.w * hv.w;
            s1 += v1.x * hv.x; s1 += v1.y * hv.y; s1 += v1.z * hv.z; s1 += v1.w * hv.w;
            s2 += v2.x * hv.x; s2 += v2.y * hv.y; s2 += v2.z * hv.z; s2 += v2.w * hv.w;
        }
        ps[r0 * 16 + b] = s0;
        ps[r1 * 16 + b] = s1;
        ps[r2 * 16 + b] = s2;
        __syncthreads();

        // elementwise LSTM cell (96 threads: one per (b, u))
        if (tid < 96) {
            float gi = ps[(0 * RC + eu) * 16 + eb];
            float gf = ps[(1 * RC + eu) * 16 + eb];
            float gc = ps[(2 * RC + eu) * 16 + eb];
            float go = ps[(3 * RC + eu) * 16 + eb];
            gi = 1.0f / (1.0f + expf(-gi));
            gf = 1.0f / (1.0f + expf(-gf));
            gc = tanhf(gc);
            go = 1.0f / (1.0f + expf(-go));
            cstate = gf * cstate + gi * gc;
            float hv = go * tanhf(cstate);
            int hid = blk * RC + eu;
            g_h[pb ^ 1][eb * HH + hid] = hv;
            out[(((size_t)(eb * NH + (hid >> 6))) * TT + t) * HD + (hid & 63)] = hv;
        }
        __syncthreads();   // all writes of this block done

        if (tid == 0) {
            __threadfence();               // publish h(t) before arriving
            atomicAdd(&g_bar, 1u);
        }
    }
}

// =======================================================================
extern "C" void kernel_launch(void* const* d_in, const int* in_sizes, int n_in,
                              void* d_out, int out_size) {
    const float* state = (const float*)d_in[0];
    const float* W_ih  = (const float*)d_in[1];
    const float* W_hh  = (const float*)d_in[2];
    const float* b_ih  = (const float*)d_in[3];
    const float* b_hh  = (const float*)d_in[4];
    float* out = (float*)d_out;

    cudaFuncSetAttribute(proj_kernel,  cudaFuncAttributeMaxDynamicSharedMemorySize, PROJ_SMEM_BYTES);
    cudaFuncSetAttribute(recur_kernel, cudaFuncAttributeMaxDynamicSharedMemorySize, RECUR_SMEM_BYTES);

    init_kernel<<<(BB * HH + 255) / 256, 256>>>();

    dim3 pgrid(G4 / PGT, TT);   // (24, 2048); x-fastest -> same-t blocks adjacent (L2 reuse)
    proj_kernel<<<pgrid, PTHREADS, PROJ_SMEM_BYTES>>>(state, W_ih, b_ih, b_hh);

    recur_kernel<<<RGRID, RTHREADS, RECUR_SMEM_BYTES>>>(W_hh, out);
}

// round 2
// speedup vs baseline: 1.0275x; 1.0275x over previous
#include <cuda_runtime.h>
#include <math.h>
#include <stdint.h>
#include <stddef.h>

#define BB 16
#define TT 2048
#define HH 768
#define G4 3072
#define NH 12
#define HD 64

// ---------------- recurrent kernel config ----------------
#define RGRID 128
#define RC 6                 // hidden units per block (768/128)
#define RROWS 24             // 4 gates * RC
#define RTHREADS 128
#define RECUR_SMEM_FLOATS (RROWS*HH + BB*772 + RROWS*BB)
#define RECUR_SMEM_BYTES (RECUR_SMEM_FLOATS * 4)

// ---------------- projection kernel config ----------------
#define PGT 128              // g rows per block
#define PKC 32               // k chunk
#define PTHREADS 128
#define PCHUNKS (HH / PKC)   // 24
#define PROJ_SMEM_FLOATS (BB*772 + 2*PGT*PKC)
#define PROJ_SMEM_BYTES (PROJ_SMEM_FLOATS * 4)

// ---------------- global scratch ----------------
__device__ float g_xg[(size_t)TT * G4 * BB];   // [t][g][b]  ~403 MB
__device__ float g_h[2][BB * HH];              // [buf][b][k]
__device__ unsigned g_flags[RGRID];            // per-CTA step flags

// ---------------- packed fp32x2 FMA helpers ----------------
__device__ __forceinline__ unsigned long long ffma2(unsigned long long a,
                                                    unsigned long long b,
                                                    unsigned long long c) {
    unsigned long long d;
    asm("fma.rn.f32x2 %0, %1, %2, %3;" : "=l"(d) : "l"(a), "l"(b), "l"(c));
    return d;
}
__device__ __forceinline__ float2 unpack2(unsigned long long v) {
    float2 r;
    asm("mov.b64 {%0, %1}, %2;" : "=f"(r.x), "=f"(r.y) : "l"(v));
    return r;
}
__device__ __forceinline__ unsigned long long pack2(float x, float y) {
    unsigned long long v;
    asm("mov.b64 %0, {%1, %2};" : "=l"(v) : "f"(x), "f"(y));
    return v;
}

// =======================================================================
// projection: xg[t][g][b] = sum_d W_ih[g][d]*x[b][t][d] + b_ih[g] + b_hh[g]
// Block (0,0) additionally zero-initializes g_h[0] and g_flags (init fold).
// grid: (G4/PGT=24, TT), 128 threads
// =======================================================================
__global__ void __launch_bounds__(PTHREADS)
proj_kernel(const float* __restrict__ state,
            const float* __restrict__ W_ih,
            const float* __restrict__ b_ih,
            const float* __restrict__ b_hh) {
    extern __shared__ float smem[];
    float*  xs    = smem;                         // [16][772]
    float4* xs4   = (float4*)xs;                  // pitch 193 f4
    float4* wbuf  = (float4*)(smem + BB * 772);   // 2 * 1024 float4 (swizzled)

    const int t   = blockIdx.y;
    const int g0  = blockIdx.x * PGT;
    const int tid = threadIdx.x;

    // folded init (runs once, before recur kernel in stream order)
    if (blockIdx.x == 0 && blockIdx.y == 0) {
        for (int i = tid; i < BB * HH; i += PTHREADS) g_h[0][i] = 0.0f;
        if (tid < RGRID) g_flags[tid] = 0u;
    }

    // load x slice for this t into smem (all 16 batches, 768 dims)
    const float4* st4 = (const float4*)state;
    #pragma unroll 4
    for (int fi = tid; fi < BB * 192; fi += PTHREADS) {
        int b  = fi / 192;
        int d4 = fi % 192;
        int head = d4 >> 4;
        int dl   = d4 & 15;
        float4 v = st4[(((size_t)(b * NH + head)) * TT + t) * 16 + dl];
        xs4[b * 193 + d4] = v;
    }

    // prefetch weight chunk 0 (XOR-swizzled)
    const float4* w4 = (const float4*)W_ih;
    for (int idx = tid; idx < PGT * 8; idx += PTHREADS) {
        int row = idx >> 3, c4 = idx & 7;
        wbuf[row * 8 + (c4 ^ ((row >> 2) & 7))] = w4[(size_t)(g0 + row) * 192 + c4];
    }

    const int tb = tid & 3;          // 4 b's per thread
    const int tg = tid >> 2;         // 4 g rows per thread
    unsigned long long acc[4][4];
    #pragma unroll
    for (int i = 0; i < 4; i++)
        #pragma unroll
        for (int j = 0; j < 4; j++) acc[i][j] = 0ull;

    int buf = 0;
    for (int c = 0; c < PCHUNKS; ++c) {
        __syncthreads();
        if (c + 1 < PCHUNKS) {
            int nb = buf ^ 1;
            #pragma unroll 2
            for (int idx = tid; idx < PGT * 8; idx += PTHREADS) {
                int row = idx >> 3, c4 = idx & 7;
                wbuf[nb * 1024 + row * 8 + (c4 ^ ((row >> 2) & 7))] =
                    w4[(size_t)(g0 + row) * 192 + (c + 1) * 8 + c4];
            }
        }
        const float4* wb = wbuf + buf * 1024;
        #pragma unroll
        for (int c4 = 0; c4 < 8; ++c4) {
            ulonglong2 wv[4];
            #pragma unroll
            for (int i = 0; i < 4; i++)
                wv[i] = *(const ulonglong2*)(wb + (4 * tg + i) * 8 + (c4 ^ (tg & 7)));
            ulonglong2 xv[4];
            #pragma unroll
            for (int j = 0; j < 4; j++)
                xv[j] = *(const ulonglong2*)(xs4 + (4 * tb + j) * 193 + c * 8 + c4);
            #pragma unroll
            for (int i = 0; i < 4; i++) {
                #pragma unroll
                for (int j = 0; j < 4; j++) {
                    acc[i][j] = ffma2(wv[i].x, xv[j].x, acc[i][j]);
                    acc[i][j] = ffma2(wv[i].y, xv[j].y, acc[i][j]);
                }
            }
        }
        buf ^= 1;
    }

    // write xg[t][g][b] (+ bias), streaming stores
    float4* xg4 = (float4*)g_xg;
    #pragma unroll
    for (int i = 0; i < 4; i++) {
        int g = g0 + 4 * tg + i;
        float bias = b_ih[g] + b_hh[g];
        float2 p0 = unpack2(acc[i][0]);
        float2 p1 = unpack2(acc[i][1]);
        float2 p2 = unpack2(acc[i][2]);
        float2 p3 = unpack2(acc[i][3]);
        float4 o;
        o.x = p0.x + p0.y + bias;
        o.y = p1.x + p1.y + bias;
        o.z = p2.x + p2.y + bias;
        o.w = p3.x + p3.y + bias;
        __stcs(&xg4[((size_t)t * G4 + g) * 4 + tb], o);
    }
}

// =======================================================================
// recurrence: 128 persistent CTAs, each owns 6 hidden units.
// Per step: flag-array barrier, stage h(t-1), FFMA2 GEMV, fast cell.
// =======================================================================
__global__ void __launch_bounds__(RTHREADS)
recur_kernel(const float* __restrict__ W_hh, float* __restrict__ out) {
    extern __shared__ float smem[];
    float*  ws  = smem;                         // [24][768]
    float4* ws4 = (float4*)ws;                  // pitch 192 f4
    float*  hs  = smem + RROWS * HH;            // [16][772]
    float4* hs4 = (float4*)hs;                  // pitch 193 f4
    float*  ps  = hs + BB * 772;                // [24][16]

    const int blk = blockIdx.x;
    const int tid = threadIdx.x;
    const int b   = tid & 15;
    const int gg  = tid >> 4;                   // 0..7

    // load this block's 24 W_hh rows into smem (row r = gate*6+u)
    const float4* wh4 = (const float4*)W_hh;
    #pragma unroll 4
    for (int idx = tid; idx < RROWS * 192; idx += RTHREADS) {
        int r  = idx / 192, c4 = idx % 192;
        int R  = (r / RC) * HH + blk * RC + (r % RC);
        ws4[r * 192 + c4] = wh4[(size_t)R * 192 + c4];
    }

    const int r0 = gg, r1 = gg + 8, r2 = gg + 16;
    const size_t xb0 = ((size_t)((r0 / RC) * HH + blk * RC + (r0 % RC))) * BB + b;
    const size_t xb1 = ((size_t)((r1 / RC) * HH + blk * RC + (r1 % RC))) * BB + b;
    const size_t xb2 = ((size_t)((r2 / RC) * HH + blk * RC + (r2 % RC))) * BB + b;

    float cstate = 0.0f;
    const int eb = tid & 15;
    const int eu = tid >> 4;   // valid when tid < 96

    volatile unsigned* vflags = (volatile unsigned*)g_flags;

    __syncthreads();

    for (int t = 0; t < TT; ++t) {
        // prefetch xg contributions (independent of the barrier), streaming
        const size_t xoff = (size_t)t * G4 * BB;
        float a0 = __ldcs(&g_xg[xoff + xb0]);
        float a1 = __ldcs(&g_xg[xoff + xb1]);
        float a2 = __ldcs(&g_xg[xoff + xb2]);

        // flag-array barrier: each thread spins on its own CTA's flag
        if (t > 0) {
            unsigned tgt = (unsigned)t;
            while (vflags[tid] < tgt) { }
            __threadfence();
        }
        __syncthreads();

        // stage h(t-1) into smem (L2-direct)
        const int pb = t & 1;
        const float4* gh4 = (const float4*)g_h[pb];
        #pragma unroll 6
        for (int idx = tid; idx < BB * 192; idx += RTHREADS) {
            int bb = idx / 192, c4 = idx % 192;
            hs4[bb * 193 + c4] = __ldcg(gh4 + bb * 192 + c4);
        }
        __syncthreads();

        // GEMV with packed FFMA2: 3 dot products of length 768 per thread
        unsigned long long s0a = pack2(a0, 0.0f), s0b = 0ull;
        unsigned long long s1a = pack2(a1, 0.0f), s1b = 0ull;
        unsigned long long s2a = pack2(a2, 0.0f), s2b = 0ull;
        const ulonglong2* hrow = (const ulonglong2*)(hs4 + b * 193);
        const ulonglong2* w0 = (const ulonglong2*)(ws4 + r0 * 192);
        const ulonglong2* w1 = (const ulonglong2*)(ws4 + r1 * 192);
        const ulonglong2* w2 = (const ulonglong2*)(ws4 + r2 * 192);
        #pragma unroll 8
        for (int k4 = 0; k4 < 192; ++k4) {
            ulonglong2 hv = hrow[k4];
            ulonglong2 v0 = w0[k4];
            ulonglong2 v1 = w1[k4];
            ulonglong2 v2 = w2[k4];
            s0a = ffma2(v0.x, hv.x, s0a); s0b = ffma2(v0.y, hv.y, s0b);
            s1a = ffma2(v1.x, hv.x, s1a); s1b = ffma2(v1.y, hv.y, s1b);
            s2a = ffma2(v2.x, hv.x, s2a); s2b = ffma2(v2.y, hv.y, s2b);
        }
        {
            float2 p, q;
            p = unpack2(s0a); q = unpack2(s0b);
            ps[r0 * 16 + b] = (p.x + p.y) + (q.x + q.y);
            p = unpack2(s1a); q = unpack2(s1b);
            ps[r1 * 16 + b] = (p.x + p.y) + (q.x + q.y);
            p = unpack2(s2a); q = unpack2(s2b);
            ps[r2 * 16 + b] = (p.x + p.y) + (q.x + q.y);
        }
        __syncthreads();

        // elementwise LSTM cell (96 threads: one per (b, u)), fast math
        if (tid < 96) {
            float gi = ps[(0 * RC + eu) * 16 + eb];
            float gf = ps[(1 * RC + eu) * 16 + eb];
            float gc = ps[(2 * RC + eu) * 16 + eb];
            float go = ps[(3 * RC + eu) * 16 + eb];
            gi = __fdividef(1.0f, 1.0f + __expf(-gi));
            gf = __fdividef(1.0f, 1.0f + __expf(-gf));
            gc = __fdividef(2.0f, 1.0f + __expf(-2.0f * gc)) - 1.0f;
            go = __fdividef(1.0f, 1.0f + __expf(-go));
            cstate = gf * cstate + gi * gc;
            float th = __fdividef(2.0f, 1.0f + __expf(-2.0f * cstate)) - 1.0f;
            float hv = go * th;
            int hid = blk * RC + eu;
            __stcg(&g_h[pb ^ 1][eb * HH + hid], hv);
            out[(((size_t)(eb * NH + (hid >> 6))) * TT + t) * HD + (hid & 63)] = hv;
        }
        __syncthreads();   // all writes of this block done

        if (tid == 0) {
            __threadfence();                       // publish h(t)
            atomicExch(&g_flags[blk], (unsigned)(t + 1));
        }
    }
}

// =======================================================================
extern "C" void kernel_launch(void* const* d_in, const int* in_sizes, int n_in,
                              void* d_out, int out_size) {
    const float* state = (const float*)d_in[0];
    const float* W_ih  = (const float*)d_in[1];
    const float* W_hh  = (const float*)d_in[2];
    const float* b_ih  = (const float*)d_in[3];
    const float* b_hh  = (const float*)d_in[4];
    float* out = (float*)d_out;

    cudaFuncSetAttribute(proj_kernel,  cudaFuncAttributeMaxDynamicSharedMemorySize, PROJ_SMEM_BYTES);
    cudaFuncSetAttribute(recur_kernel, cudaFuncAttributeMaxDynamicSharedMemorySize, RECUR_SMEM_BYTES);

    dim3 pgrid(G4 / PGT, TT);   // (24, 2048)
    proj_kernel<<<pgrid, PTHREADS, PROJ_SMEM_BYTES>>>(state, W_ih, b_ih, b_hh);

    recur_kernel<<<RGRID, RTHREADS, RECUR_SMEM_BYTES>>>(W_hh, out);
}

// round 3
// speedup vs baseline: 1.2723x; 1.2382x over previous
#include <cuda_runtime.h>
#include <math.h>
#include <stdint.h>
#include <stddef.h>

#define BB 16
#define TT 2048
#define HH 768
#define G4 3072
#define NH 12
#define HD 64

// ---------------- recurrent kernel config ----------------
#define RGRID 128
#define RC 6                 // hidden units per block (768/128)
#define RROWS 24             // 4 gates * RC
#define RTHREADS 128
#define WPITCH 780           // ws row pitch: 3*780 % 32 == 4 -> rg*4 banks, conflict-free
#define HPITCH 776           // hs row pitch: 776 % 32 == 8  -> b-stride 8 banks, conflict-free
#define KSLICE 192           // k per warp (768/4)
#define RECUR_SMEM_FLOATS (RROWS*WPITCH + BB*HPITCH + 4*RROWS*BB)
#define RECUR_SMEM_BYTES (RECUR_SMEM_FLOATS * 4)

// ---------------- projection kernel config ----------------
#define PGT 128              // g rows per block
#define PKC 32               // k chunk
#define PTHREADS 128
#define PCHUNKS (HH / PKC)   // 24
#define PROJ_SMEM_FLOATS (BB*772 + 2*PGT*PKC)
#define PROJ_SMEM_BYTES (PROJ_SMEM_FLOATS * 4)

// ---------------- global scratch ----------------
__device__ float g_xg[(size_t)TT * G4 * BB];   // [t][g][b]  ~403 MB
__device__ float g_h[2][BB * HH];              // [buf][b][k]
__device__ unsigned g_flags[RGRID];            // per-CTA step flags

// ---------------- packed fp32x2 FMA helpers ----------------
__device__ __forceinline__ unsigned long long ffma2(unsigned long long a,
                                                    unsigned long long b,
                                                    unsigned long long c) {
    unsigned long long d;
    asm("fma.rn.f32x2 %0, %1, %2, %3;" : "=l"(d) : "l"(a), "l"(b), "l"(c));
    return d;
}
__device__ __forceinline__ float2 unpack2(unsigned long long v) {
    float2 r;
    asm("mov.b64 {%0, %1}, %2;" : "=f"(r.x), "=f"(r.y) : "l"(v));
    return r;
}

// =======================================================================
// projection: xg[t][g][b] = sum_d W_ih[g][d]*x[b][t][d] + b_ih[g] + b_hh[g]
// Block (0,0) additionally zero-initializes g_h[0] and g_flags.
// grid: (24, 2048), 128 threads
// =======================================================================
__global__ void __launch_bounds__(PTHREADS)
proj_kernel(const float* __restrict__ state,
            const float* __restrict__ W_ih,
            const float* __restrict__ b_ih,
            const float* __restrict__ b_hh) {
    extern __shared__ float smem[];
    float*  xs    = smem;                         // [16][772]
    float4* xs4   = (float4*)xs;                  // pitch 193 f4
    float4* wbuf  = (float4*)(smem + BB * 772);   // 2 * 1024 float4 (swizzled)

    const int t   = blockIdx.y;
    const int g0  = blockIdx.x * PGT;
    const int tid = threadIdx.x;

    if (blockIdx.x == 0 && blockIdx.y == 0) {
        for (int i = tid; i < BB * HH; i += PTHREADS) g_h[0][i] = 0.0f;
        if (tid < RGRID) g_flags[tid] = 0u;
    }

    const float4* st4 = (const float4*)state;
    #pragma unroll 4
    for (int fi = tid; fi < BB * 192; fi += PTHREADS) {
        int b  = fi / 192;
        int d4 = fi % 192;
        int head = d4 >> 4;
        int dl   = d4 & 15;
        float4 v = st4[(((size_t)(b * NH + head)) * TT + t) * 16 + dl];
        xs4[b * 193 + d4] = v;
    }

    const float4* w4 = (const float4*)W_ih;
    for (int idx = tid; idx < PGT * 8; idx += PTHREADS) {
        int row = idx >> 3, c4 = idx & 7;
        wbuf[row * 8 + (c4 ^ ((row >> 2) & 7))] = w4[(size_t)(g0 + row) * 192 + c4];
    }

    const int tb = tid & 3;
    const int tg = tid >> 2;
    unsigned long long acc[4][4];
    #pragma unroll
    for (int i = 0; i < 4; i++)
        #pragma unroll
        for (int j = 0; j < 4; j++) acc[i][j] = 0ull;

    int buf = 0;
    for (int c = 0; c < PCHUNKS; ++c) {
        __syncthreads();
        if (c + 1 < PCHUNKS) {
            int nb = buf ^ 1;
            #pragma unroll 2
            for (int idx = tid; idx < PGT * 8; idx += PTHREADS) {
                int row = idx >> 3, c4 = idx & 7;
                wbuf[nb * 1024 + row * 8 + (c4 ^ ((row >> 2) & 7))] =
                    w4[(size_t)(g0 + row) * 192 + (c + 1) * 8 + c4];
            }
        }
        const float4* wb = wbuf + buf * 1024;
        #pragma unroll
        for (int c4 = 0; c4 < 8; ++c4) {
            ulonglong2 wv[4];
            #pragma unroll
            for (int i = 0; i < 4; i++)
                wv[i] = *(const ulonglong2*)(wb + (4 * tg + i) * 8 + (c4 ^ (tg & 7)));
            ulonglong2 xv[4];
            #pragma unroll
            for (int j = 0; j < 4; j++)
                xv[j] = *(const ulonglong2*)(xs4 + (4 * tb + j) * 193 + c * 8 + c4);
            #pragma unroll
            for (int i = 0; i < 4; i++) {
                #pragma unroll
                for (int j = 0; j < 4; j++) {
                    acc[i][j] = ffma2(wv[i].x, xv[j].x, acc[i][j]);
                    acc[i][j] = ffma2(wv[i].y, xv[j].y, acc[i][j]);
                }
            }
        }
        buf ^= 1;
    }

    float4* xg4 = (float4*)g_xg;
    #pragma unroll
    for (int i = 0; i < 4; i++) {
        int g = g0 + 4 * tg + i;
        float bias = b_ih[g] + b_hh[g];
        float2 p0 = unpack2(acc[i][0]);
        float2 p1 = unpack2(acc[i][1]);
        float2 p2 = unpack2(acc[i][2]);
        float2 p3 = unpack2(acc[i][3]);
        float4 o;
        o.x = p0.x + p0.y + bias;
        o.y = p1.x + p1.y + bias;
        o.z = p2.x + p2.y + bias;
        o.w = p3.x + p3.y + bias;
        __stcs(&xg4[((size_t)t * G4 + g) * 4 + tb], o);
    }
}

// =======================================================================
// recurrence: 128 persistent CTAs, 24 rows each, register-tiled split-K.
// warp = k-slice (192), lane = (rg: 3 rows, bg: 4 strided batches).
// =======================================================================
__global__ void __launch_bounds__(RTHREADS)
recur_kernel(const float* __restrict__ W_hh, float* __restrict__ out) {
    extern __shared__ float smem[];
    float* ws = smem;                          // [24][WPITCH]
    float* hs = smem + RROWS * WPITCH;         // [16][HPITCH]
    float* pr = hs + BB * HPITCH;              // [4][24][16] partials

    const int blk  = blockIdx.x;
    const int tid  = threadIdx.x;
    const int lane = tid & 31;
    const int wrp  = tid >> 5;                 // 0..3 : k-slice
    const int rg   = lane >> 2;                // 0..7 : rows 3rg..3rg+2
    const int bg   = lane & 3;                 // batches bg, bg+4, bg+8, bg+12

    // load 24 W_hh rows into smem (row r = gate*6+u), pitch WPITCH
    const float4* wh4 = (const float4*)W_hh;
    #pragma unroll 4
    for (int idx = tid; idx < RROWS * 192; idx += RTHREADS) {
        int r  = idx / 192, c4 = idx % 192;
        int R  = (r / RC) * HH + blk * RC + (r % RC);
        *(float4*)(ws + r * WPITCH + c4 * 4) = wh4[(size_t)R * 192 + c4];
    }

    // cell threads (tid < 96): eu = unit, eb = batch
    const int eb = tid & 15;
    const int eu = tid >> 4;
    float cstate = 0.0f;

    volatile unsigned* vflags = (volatile unsigned*)g_flags;

    __syncthreads();

    for (int t = 0; t < TT; ++t) {
        // prefetch xg gate contributions (in flight across the barrier)
        float a[4];
        if (tid < 96) {
            const size_t xoff = (size_t)t * G4 * BB;
            #pragma unroll
            for (int q = 0; q < 4; ++q)
                a[q] = __ldcs(&g_xg[xoff + (size_t)(q * HH + blk * RC + eu) * BB + eb]);
        }

        // global barrier: every thread spins on one CTA's flag
        if (t > 0) {
            unsigned tgt = (unsigned)t;
            while (vflags[tid] < tgt) { }
            __threadfence();
        }
        __syncthreads();

        // per-warp staging of this warp's h k-slice (12KB), batched for MLP
        const int pb = t & 1;
        {
            const float4* src = (const float4*)g_h[pb];   // [b][192 f4]
            float4 tmp[12];
            #pragma unroll
            for (int i = 0; i < 12; ++i) {
                int idx = i * 32 + lane;                   // 0..383
                int b = idx / 48, k4 = idx % 48;
                tmp[i] = __ldcg(src + b * 192 + wrp * 48 + k4);
            }
            #pragma unroll
            for (int i = 0; i < 12; ++i) {
                int idx = i * 32 + lane;
                int b = idx / 48, k4 = idx % 48;
                *(float4*)(hs + b * HPITCH + wrp * KSLICE + k4 * 4) = tmp[i];
            }
            #pragma unroll
            for (int i = 0; i < 12; ++i) {
                int idx = 384 + i * 32 + lane;             // 384..767
                int b = idx / 48, k4 = idx % 48;
                tmp[i] = __ldcg(src + b * 192 + wrp * 48 + k4);
            }
            #pragma unroll
            for (int i = 0; i < 12; ++i) {
                int idx = 384 + i * 32 + lane;
                int b = idx / 48, k4 = idx % 48;
                *(float4*)(hs + b * HPITCH + wrp * KSLICE + k4 * 4) = tmp[i];
            }
        }
        __syncwarp();   // only this warp reads its slice

        // GEMV: 3 rows x 4 batches x 192 k per thread, packed FFMA2
        unsigned long long acc[3][4];
        #pragma unroll
        for (int i = 0; i < 3; i++)
            #pragma unroll
            for (int j = 0; j < 4; j++) acc[i][j] = 0ull;

        const float* wbase = ws + wrp * KSLICE;
        const float* hbase = hs + wrp * KSLICE;
        #pragma unroll 8
        for (int k4 = 0; k4 < 48; ++k4) {
            ulonglong2 wv[3];
            #pragma unroll
            for (int i = 0; i < 3; i++)
                wv[i] = *(const ulonglong2*)(wbase + (3 * rg + i) * WPITCH + 4 * k4);
            ulonglong2 hv[4];
            #pragma unroll
            for (int j = 0; j < 4; j++)
                hv[j] = *(const ulonglong2*)(hbase + (bg + 4 * j) * HPITCH + 4 * k4);
            #pragma unroll
            for (int i = 0; i < 3; i++) {
                #pragma unroll
                for (int j = 0; j < 4; j++) {
                    acc[i][j] = ffma2(wv[i].x, hv[j].x, acc[i][j]);
                    acc[i][j] = ffma2(wv[i].y, hv[j].y, acc[i][j]);
                }
            }
        }

        // write partials: pr[warp][row][batch]
        #pragma unroll
        for (int i = 0; i < 3; i++) {
            #pragma unroll
            for (int j = 0; j < 4; j++) {
                float2 p = unpack2(acc[i][j]);
                pr[(wrp * RROWS + 3 * rg + i) * BB + (bg + 4 * j)] = p.x + p.y;
            }
        }
        __syncthreads();

        // reduce 4 warps + cell (96 threads)
        if (tid < 96) {
            float gs[4];
            #pragma unroll
            for (int q = 0; q < 4; ++q) {
                int r = q * RC + eu;
                float s = a[q];
                #pragma unroll
                for (int w = 0; w < 4; ++w) s += pr[(w * RROWS + r) * BB + eb];
                gs[q] = s;
            }
            float gi = __fdividef(1.0f, 1.0f + __expf(-gs[0]));
            float gf = __fdividef(1.0f, 1.0f + __expf(-gs[1]));
            float gc = __fdividef(2.0f, 1.0f + __expf(-2.0f * gs[2])) - 1.0f;
            float go = __fdividef(1.0f, 1.0f + __expf(-gs[3]));
            cstate = gf * cstate + gi * gc;
            float th = __fdividef(2.0f, 1.0f + __expf(-2.0f * cstate)) - 1.0f;
            float hv = go * th;
            int hid = blk * RC + eu;
            __stcg(&g_h[pb ^ 1][eb * HH + hid], hv);
            __stcs(&out[(((size_t)(eb * NH + (hid >> 6))) * TT + t) * HD + (hid & 63)], hv);
        }
        __syncthreads();   // h/out/pr-reads done

        if (tid == 0) {
            __threadfence();
            atomicExch(&g_flags[blk], (unsigned)(t + 1));
        }
    }
}

// =======================================================================
extern "C" void kernel_launch(void* const* d_in, const int* in_sizes, int n_in,
                              void* d_out, int out_size) {
    const float* state = (const float*)d_in[0];
    const float* W_ih  = (const float*)d_in[1];
    const float* W_hh  = (const float*)d_in[2];
    const float* b_ih  = (const float*)d_in[3];
    const float* b_hh  = (const float*)d_in[4];
    float* out = (float*)d_out;

    cudaFuncSetAttribute(proj_kernel,  cudaFuncAttributeMaxDynamicSharedMemorySize, PROJ_SMEM_BYTES);
    cudaFuncSetAttribute(recur_kernel, cudaFuncAttributeMaxDynamicSharedMemorySize, RECUR_SMEM_BYTES);

    dim3 pgrid(G4 / PGT, TT);   // (24, 2048)
    proj_kernel<<<pgrid, PTHREADS, PROJ_SMEM_BYTES>>>(state, W_ih, b_ih, b_hh);

    recur_kernel<<<RGRID, RTHREADS, RECUR_SMEM_BYTES>>>(W_hh, out);
}

// round 4
// speedup vs baseline: 1.7267x; 1.3572x over previous
#include <cuda_runtime.h>
#include <math.h>
#include <stdint.h>
#include <stddef.h>

#define BB 16
#define TT 2048
#define HH 768
#define G4 3072
#define NH 12
#define HD 64

// ---------------- recurrent kernel config ----------------
#define RGRID 128
#define RC 6                  // hidden units per block
#define RROWS 24              // 4 gates * RC
#define RTHREADS 128
#define SLICES 16             // k-split
#define SLICE_K 48            // k per slice
#define SLICE_P 52            // padded slice pitch (floats); 13 f4, odd -> conflict-free
#define ROWP (SLICES * SLICE_P)   // 832 floats: pitch for ws rows and hs batches
#define PRP 385               // partial array slice pitch (floats), odd -> conflict-free
#define RECUR_SMEM_FLOATS (RROWS*ROWP + BB*ROWP + SLICES*PRP + 32)
#define RECUR_SMEM_BYTES (RECUR_SMEM_FLOATS * 4)

// ---------------- projection kernel config ----------------
#define PGT 256               // g rows per block
#define PKC 32                // k chunk
#define PTHREADS 128
#define PCHUNKS (HH / PKC)    // 24
#define PROJ_SMEM_FLOATS (BB*772 + 2*PGT*PKC)
#define PROJ_SMEM_BYTES (PROJ_SMEM_FLOATS * 4)

// ---------------- global scratch ----------------
__device__ float g_xg[(size_t)TT * G4 * BB];   // [t][g][b]  ~403 MB
__device__ float g_h[2][BB * HH];              // [buf][b][k]
__device__ unsigned g_flags[RGRID];            // per-CTA step flags

// ---------------- packed fp32x2 FMA helpers ----------------
__device__ __forceinline__ unsigned long long ffma2(unsigned long long a,
                                                    unsigned long long b,
                                                    unsigned long long c) {
    unsigned long long d;
    asm("fma.rn.f32x2 %0, %1, %2, %3;" : "=l"(d) : "l"(a), "l"(b), "l"(c));
    return d;
}
__device__ __forceinline__ float2 unpack2(unsigned long long v) {
    float2 r;
    asm("mov.b64 {%0, %1}, %2;" : "=f"(r.x), "=f"(r.y) : "l"(v));
    return r;
}

// =======================================================================
// projection: xg[t][g][b] = sum_d W_ih[g][d]*x[b][t][d] + b_ih[g] + b_hh[g]
// CTA tile: 256 g x 16 b x 768 k; thread tile 8g x 4b (strided b).
// grid: (12, 2048), 128 threads. Block (0,0) also zero-inits h/flags.
// =======================================================================
__global__ void __launch_bounds__(PTHREADS)
proj_kernel(const float* __restrict__ state,
            const float* __restrict__ W_ih,
            const float* __restrict__ b_ih,
            const float* __restrict__ b_hh) {
    extern __shared__ float smem[];
    float4* xs4  = (float4*)smem;                 // [16][193] f4
    float4* wbuf = (float4*)(smem + BB * 772);    // 2 * 2048 f4, swizzled

    const int t   = blockIdx.y;
    const int g0  = blockIdx.x * PGT;
    const int tid = threadIdx.x;

    if (blockIdx.x == 0 && blockIdx.y == 0) {
        for (int i = tid; i < BB * HH; i += PTHREADS) g_h[0][i] = 0.0f;
        if (tid < RGRID) g_flags[tid] = 0u;
    }

    // load x slice for this t
    const float4* st4 = (const float4*)state;
    #pragma unroll 4
    for (int fi = tid; fi < BB * 192; fi += PTHREADS) {
        int b  = fi / 192;
        int d4 = fi % 192;
        int head = d4 >> 4;
        int dl   = d4 & 15;
        xs4[b * 193 + d4] = st4[(((size_t)(b * NH + head)) * TT + t) * 16 + dl];
    }

    // prefetch weight chunk 0 (swizzle: c4 ^ (row>>3 & 7))
    const float4* w4 = (const float4*)W_ih;
    #pragma unroll 4
    for (int idx = tid; idx < PGT * 8; idx += PTHREADS) {
        int row = idx >> 3, c4 = idx & 7;
        wbuf[row * 8 + (c4 ^ ((row >> 3) & 7))] = w4[(size_t)(g0 + row) * 192 + c4];
    }

    const int tb = tid & 3;          // b = tb + 4j (strided)
    const int tg = tid >> 2;         // 0..31 : rows 8tg..8tg+7
    unsigned long long acc[8][4];
    #pragma unroll
    for (int i = 0; i < 8; i++)
        #pragma unroll
        for (int j = 0; j < 4; j++) acc[i][j] = 0ull;

    int buf = 0;
    for (int c = 0; c < PCHUNKS; ++c) {
        __syncthreads();
        if (c + 1 < PCHUNKS) {
            int nb = buf ^ 1;
            #pragma unroll 4
            for (int idx = tid; idx < PGT * 8; idx += PTHREADS) {
                int row = idx >> 3, c4 = idx & 7;
                wbuf[nb * 2048 + row * 8 + (c4 ^ ((row >> 3) & 7))] =
                    w4[(size_t)(g0 + row) * 192 + (c + 1) * 8 + c4];
            }
        }
        const float4* wb = wbuf + buf * 2048;
        #pragma unroll
        for (int c4 = 0; c4 < 8; ++c4) {
            ulonglong2 wv[8];
            #pragma unroll
            for (int i = 0; i < 8; i++)
                wv[i] = *(const ulonglong2*)(wb + (8 * tg + i) * 8 + (c4 ^ (tg & 7)));
            ulonglong2 xv[4];
            #pragma unroll
            for (int j = 0; j < 4; j++)
                xv[j] = *(const ulonglong2*)(xs4 + (tb + 4 * j) * 193 + c * 8 + c4);
            #pragma unroll
            for (int i = 0; i < 8; i++) {
                #pragma unroll
                for (int j = 0; j < 4; j++) {
                    acc[i][j] = ffma2(wv[i].x, xv[j].x, acc[i][j]);
                    acc[i][j] = ffma2(wv[i].y, xv[j].y, acc[i][j]);
                }
            }
        }
        buf ^= 1;
    }

    // store: 8 rows x 4 strided b, scalar
    #pragma unroll
    for (int i = 0; i < 8; i++) {
        int g = g0 + 8 * tg + i;
        float bias = b_ih[g] + b_hh[g];
        size_t base = ((size_t)t * G4 + g) * BB;
        #pragma unroll
        for (int j = 0; j < 4; j++) {
            float2 p = unpack2(acc[i][j]);
            __stcs(&g_xg[base + (tb + 4 * j)], p.x + p.y + bias);
        }
    }
}

// =======================================================================
// recurrence: 128 persistent CTAs, 24 rows each.
// warp = gate (6 rows); lane = (batch-half j, k-slice s of 48 k).
// Thread tile: 6 rows x 8 batches x 48 k. 16-way k-split reduced in smem.
// =======================================================================
__global__ void __launch_bounds__(RTHREADS)
recur_kernel(const float* __restrict__ W_hh, float* __restrict__ out) {
    extern __shared__ float smem[];
    float* ws = smem;                          // [24][ROWP]
    float* hs = smem + RROWS * ROWP;           // [16][ROWP]
    float* pr = hs + BB * ROWP;                // [16 slices][PRP]

    const int blk  = blockIdx.x;
    const int tid  = threadIdx.x;
    const int lane = tid & 31;
    const int wrp  = tid >> 5;                 // gate / row-group
    const int s    = lane & 15;                // k-slice
    const int j    = lane >> 4;                // batch half

    // load 24 W_hh rows into sliced layout: ws[r][sl*52 + kk]
    const float4* wh4 = (const float4*)W_hh;
    #pragma unroll 4
    for (int idx = tid; idx < RROWS * 192; idx += RTHREADS) {
        int r  = idx / 192, f4 = idx % 192;
        int gr = (r / RC) * HH + blk * RC + (r % RC);
        int sl = f4 / 12, kk = f4 % 12;
        *(float4*)(ws + r * ROWP + sl * SLICE_P + kk * 4) = wh4[(size_t)gr * 192 + f4];
    }

    // cell threads (tid < 96)
    const int eb = tid & 15;
    const int eu = tid >> 4;
    float cstate = 0.0f;

    volatile unsigned* vflags = (volatile unsigned*)g_flags;

    __syncthreads();

    for (int t = 0; t < TT; ++t) {
        // prefetch xg gate contributions (in flight across the barrier)
        float a[4];
        if (tid < 96) {
            const size_t xoff = (size_t)t * G4 * BB;
            #pragma unroll
            for (int q = 0; q < 4; ++q)
                a[q] = __ldcs(&g_xg[xoff + (size_t)(q * HH + blk * RC + eu) * BB + eb]);
        }

        // global barrier
        if (t > 0) {
            unsigned tgt = (unsigned)t;
            while (vflags[tid] < tgt) { }
            __threadfence();
        }
        __syncthreads();

        // stage h(t-1): warp w stages batches 4w..4w+3 into sliced layout
        const int pb = t & 1;
        {
            const float4* src = (const float4*)g_h[pb];   // [b][192 f4]
            #pragma unroll
            for (int pass = 0; pass < 2; ++pass) {
                float4 tmp[12];
                #pragma unroll
                for (int i = 0; i < 12; ++i) {
                    int idx = pass * 384 + i * 32 + lane;  // 0..767
                    int bl = idx / 192, f4 = idx % 192;
                    tmp[i] = __ldcg(src + (4 * wrp + bl) * 192 + f4);
                }
                #pragma unroll
                for (int i = 0; i < 12; ++i) {
                    int idx = pass * 384 + i * 32 + lane;
                    int bl = idx / 192, f4 = idx % 192;
                    int sl = f4 / 12, kk = f4 % 12;
                    *(float4*)(hs + (4 * wrp + bl) * ROWP + sl * SLICE_P + kk * 4) = tmp[i];
                }
            }
        }
        __syncthreads();

        // GEMV: 6 rows x 8 batches x 48 k per thread (packed FFMA2)
        unsigned long long acc[6][8];
        #pragma unroll
        for (int i = 0; i < 6; i++)
            #pragma unroll
            for (int m = 0; m < 8; m++) acc[i][m] = 0ull;

        const float* wbase = ws + (6 * wrp) * ROWP + s * SLICE_P;
        const float* hbase = hs + (8 * j) * ROWP + s * SLICE_P;
        #pragma unroll 4
        for (int k4 = 0; k4 < 12; ++k4) {
            ulonglong2 wv[6];
            #pragma unroll
            for (int i = 0; i < 6; i++)
                wv[i] = *(const ulonglong2*)(wbase + i * ROWP + 4 * k4);
            ulonglong2 hv[8];
            #pragma unroll
            for (int m = 0; m < 8; m++)
                hv[m] = *(const ulonglong2*)(hbase + m * ROWP + 4 * k4);
            #pragma unroll
            for (int i = 0; i < 6; i++) {
                #pragma unroll
                for (int m = 0; m < 8; m++) {
                    acc[i][m] = ffma2(wv[i].x, hv[m].x, acc[i][m]);
                    acc[i][m] = ffma2(wv[i].y, hv[m].y, acc[i][m]);
                }
            }
        }

        // partials: pr[s][row*16 + b]
        #pragma unroll
        for (int i = 0; i < 6; i++) {
            #pragma unroll
            for (int m = 0; m < 8; m++) {
                float2 p = unpack2(acc[i][m]);
                pr[s * PRP + (6 * wrp + i) * BB + (8 * j + m)] = p.x + p.y;
            }
        }
        __syncthreads();

        // reduce 16 slices + cell (96 threads)
        if (tid < 96) {
            float gs[4];
            #pragma unroll
            for (int q = 0; q < 4; ++q) {
                float sum = a[q];
                int ro = (q * RC + eu) * BB + eb;
                #pragma unroll
                for (int ss = 0; ss < 16; ++ss) sum += pr[ss * PRP + ro];
                gs[q] = sum;
            }
            float gi = __fdividef(1.0f, 1.0f + __expf(-gs[0]));
            float gf = __fdividef(1.0f, 1.0f + __expf(-gs[1]));
            float gc = __fdividef(2.0f, 1.0f + __expf(-2.0f * gs[2])) - 1.0f;
            float go = __fdividef(1.0f, 1.0f + __expf(-gs[3]));
            cstate = gf * cstate + gi * gc;
            float th = __fdividef(2.0f, 1.0f + __expf(-2.0f * cstate)) - 1.0f;
            float hv = go * th;
            int hid = blk * RC + eu;
            __stcg(&g_h[pb ^ 1][eb * HH + hid], hv);
            __stcs(&out[(((size_t)(eb * NH + (hid >> 6))) * TT + t) * HD + (hid & 63)], hv);
        }
        __syncthreads();

        if (tid == 0) {
            __threadfence();
            atomicExch(&g_flags[blk], (unsigned)(t + 1));
        }
    }
}

// =======================================================================
extern "C" void kernel_launch(void* const* d_in, const int* in_sizes, int n_in,
                              void* d_out, int out_size) {
    const float* state = (const float*)d_in[0];
    const float* W_ih  = (const float*)d_in[1];
    const float* W_hh  = (const float*)d_in[2];
    const float* b_ih  = (const float*)d_in[3];
    const float* b_hh  = (const float*)d_in[4];
    float* out = (float*)d_out;

    cudaFuncSetAttribute(proj_kernel,  cudaFuncAttributeMaxDynamicSharedMemorySize, PROJ_SMEM_BYTES);
    cudaFuncSetAttribute(recur_kernel, cudaFuncAttributeMaxDynamicSharedMemorySize, RECUR_SMEM_BYTES);

    dim3 pgrid(G4 / PGT, TT);   // (12, 2048)
    proj_kernel<<<pgrid, PTHREADS, PROJ_SMEM_BYTES>>>(state, W_ih, b_ih, b_hh);

    recur_kernel<<<RGRID, RTHREADS, RECUR_SMEM_BYTES>>>(W_hh, out);
}